// round 9
// baseline (speedup 1.0000x reference)
#include <cuda_runtime.h>
#include <cuda_bf16.h>
#include <cstdint>
#include <math.h>

// Problem dims (fixed by reference)
#define BB 8
#define LL 2048
#define DIN 512
#define HH 1024
#define NS 16
#define RR 64
#define MM (BB * LL)   // 16384

typedef __nv_bfloat16 bf16;

// ---------------- scratch (device globals; no allocation allowed) ----------
__device__ bf16  g_xn16 [(size_t)MM * DIN];
__device__ bf16  g_h16  [(size_t)MM * HH];
__device__ bf16  g_hc16 [(size_t)MM * HH];
__device__ bf16  g_dtr16[(size_t)MM * RR];
__device__ bf16  g_dt16 [(size_t)MM * HH];
__device__ bf16  g_y16  [(size_t)MM * HH];
__device__ bf16  g_win16 [(size_t)HH * DIN];
__device__ bf16  g_w1_16 [(size_t)RR * HH];
__device__ bf16  g_w2_16 [(size_t)HH * RR];
__device__ bf16  g_wout16[(size_t)DIN * HH];

// ---------------- helpers ---------------------------------------------------
__device__ __forceinline__ float blockReduce128(float v, float* sh) {
    #pragma unroll
    for (int o = 16; o > 0; o >>= 1) v += __shfl_xor_sync(0xffffffffu, v, o);
    int w = threadIdx.x >> 5;
    if ((threadIdx.x & 31) == 0) sh[w] = v;
    __syncthreads();
    float r = sh[0] + sh[1] + sh[2] + sh[3];
    __syncthreads();
    return r;
}

__device__ __forceinline__ float softplusf(float v) {
    return (v > 20.f) ? v : log1pf(expf(v));
}

__device__ __forceinline__ void cp_async16(uint32_t saddr, const void* gptr, bool pred) {
    int sz = pred ? 16 : 0;
    asm volatile("cp.async.cg.shared.global [%0], [%1], 16, %2;\n"
                 :: "r"(saddr), "l"(gptr), "r"(sz));
}
__device__ __forceinline__ void cp_commit() {
    asm volatile("cp.async.commit_group;\n" ::: "memory");
}
__device__ __forceinline__ void cp_wait1() {
    asm volatile("cp.async.wait_group 1;\n" ::: "memory");
}

// ---------------- merged f32 -> bf16 weight conversion ----------------------
#define SEG0 (HH*DIN)                 // 524288
#define SEG1 (SEG0 + RR*HH)           // 589824
#define SEG2 (SEG1 + HH*RR)           // 655360
#define SEG3 (SEG2 + DIN*HH)          // 1179648
__global__ void f2bf4_kernel(const float* __restrict__ s0, const float* __restrict__ s1,
                             const float* __restrict__ s2, const float* __restrict__ s3,
                             bf16* __restrict__ d0, bf16* __restrict__ d1,
                             bf16* __restrict__ d2, bf16* __restrict__ d3) {
    int i = (blockIdx.x * blockDim.x + threadIdx.x) * 4;
    if (i >= SEG3) return;
    const float* s; bf16* d; int off;
    if      (i < SEG0) { s = s0; d = d0; off = i; }
    else if (i < SEG1) { s = s1; d = d1; off = i - SEG0; }
    else if (i < SEG2) { s = s2; d = d2; off = i - SEG1; }
    else               { s = s3; d = d3; off = i - SEG2; }
    float4 v = *(const float4*)(s + off);
    __nv_bfloat162* o = (__nv_bfloat162*)(d + off);
    o[0] = __floats2bfloat162_rn(v.x, v.y);
    o[1] = __floats2bfloat162_rn(v.z, v.w);
}

// ---------------- LayerNorm: one block (128 thr) per row of 512 -------------
__global__ void ln_kernel(const float* __restrict__ x,
                          const float* __restrict__ gamma,
                          const float* __restrict__ beta,
                          bf16* __restrict__ out) {
    __shared__ float sh[4];
    size_t row = blockIdx.x;
    const float4* xr = (const float4*)(x + row * DIN);
    float4 v = xr[threadIdx.x];
    float s = blockReduce128(v.x + v.y + v.z + v.w, sh);
    float mu = s * (1.f / DIN);
    float dx = v.x - mu, dy = v.y - mu, dz = v.z - mu, dw = v.w - mu;
    float s2 = blockReduce128(dx*dx + dy*dy + dz*dz + dw*dw, sh);
    float rstd = rsqrtf(s2 * (1.f / DIN) + 1e-5f);
    float4 gv = ((const float4*)gamma)[threadIdx.x];
    float4 bv = ((const float4*)beta )[threadIdx.x];
    __nv_bfloat162* orow = (__nv_bfloat162*)(out + row * DIN);
    orow[2*threadIdx.x + 0] = __floats2bfloat162_rn(dx * rstd * gv.x + bv.x,
                                                    dy * rstd * gv.y + bv.y);
    orow[2*threadIdx.x + 1] = __floats2bfloat162_rn(dz * rstd * gv.z + bv.z,
                                                    dw * rstd * gv.w + bv.w);
}

// ---------------- MMA primitives --------------------------------------------
__device__ __forceinline__ void ldsm_x4(uint32_t& r0, uint32_t& r1,
                                        uint32_t& r2, uint32_t& r3,
                                        uint32_t addr) {
    asm volatile("ldmatrix.sync.aligned.m8n8.x4.shared.b16 {%0,%1,%2,%3}, [%4];"
                 : "=r"(r0), "=r"(r1), "=r"(r2), "=r"(r3) : "r"(addr));
}

__device__ __forceinline__ void mma_bf16(float* c4, const uint32_t* af,
                                         uint32_t b0, uint32_t b1) {
    asm volatile(
        "mma.sync.aligned.m16n8k16.row.col.f32.bf16.bf16.f32 "
        "{%0,%1,%2,%3}, {%4,%5,%6,%7}, {%8,%9}, {%0,%1,%2,%3};"
        : "+f"(c4[0]), "+f"(c4[1]), "+f"(c4[2]), "+f"(c4[3])
        : "r"(af[0]), "r"(af[1]), "r"(af[2]), "r"(af[3]), "r"(b0), "r"(b1));
}

// ---------------- bf16 tensor-core GEMM: C[M,N] = A[M,K] * B[N,K]^T ---------
// 128x128 tile, BK=32, 3-stage cp.async pipeline, one __syncthreads per k-tile.
// Unpadded 64B rows + XOR chunk swizzle: physical_chunk = chunk ^ ((row>>1)&3).
// EPI: 0 = none (bf16 out), 1 = bias+ReLU (bf16), 2 = bias+softplus (bf16),
//      3 = +residual (f32 out)
#define STAGE_BYTES 8192    // 128 rows * 64 bytes
template <int EPI, typename OutT>
__global__ __launch_bounds__(256)
void gemm_bf16(const bf16* __restrict__ A, const bf16* __restrict__ B,
               const float* __restrict__ bias, const float* __restrict__ res,
               OutT* __restrict__ C, int M, int N, int K) {
    __shared__ bf16 smemAll[3 * 2 * 4096];   // 49152 B: A stages 0-2, then B stages 0-2

    const int tid  = threadIdx.x;
    const int lane = tid & 31;
    const int wid  = tid >> 5;
    const int wRow = wid >> 2;      // 0..1
    const int wCol = wid & 3;       // 0..3
    const int bM = blockIdx.y * 128;
    const int bN = blockIdx.x * 128;

    const uint32_t sA0 = (uint32_t)__cvta_generic_to_shared(smemAll);
    const uint32_t sB0 = sA0 + 3 * STAGE_BYTES;

    // staging: thread writes rows (tid>>2) and (tid>>2)+64, chunk tid&3 (swizzled)
    const int ldR0 = tid >> 2;
    const int ldC  = (tid & 3) * 8;                 // gmem half offset
    const int ldPC = (tid & 3) ^ ((ldR0 >> 1) & 3); // physical chunk (same for +64)
    const uint32_t ldOff0 = (uint32_t)(ldR0 * 64 + ldPC * 16);
    const uint32_t ldOff1 = ldOff0 + 64 * 64;

    // ldmatrix lane addresses, precomputed per (tile, kk-half): XOR swizzle
    uint32_t aAddr[4][2], bAddr[2][2];
    {
        const int ar = lane & 15, cbA = lane >> 4;
        #pragma unroll
        for (int mi = 0; mi < 4; mi++) {
            int row = wRow*64 + mi*16 + ar;
            int sw = (row >> 1) & 3;
            #pragma unroll
            for (int kki = 0; kki < 2; kki++) {
                int pc = (cbA + kki*2) ^ sw;
                aAddr[mi][kki] = sA0 + (uint32_t)(row * 64 + pc * 16);
            }
        }
        const int br = ((lane >> 4) << 3) + (lane & 7);
        const int cbB = (lane >> 3) & 1;
        #pragma unroll
        for (int p = 0; p < 2; p++) {
            int row = wCol*32 + p*16 + br;
            int sw = (row >> 1) & 3;
            #pragma unroll
            for (int kki = 0; kki < 2; kki++) {
                int pc = (cbB + kki*2) ^ sw;
                bAddr[p][kki] = sB0 + (uint32_t)(row * 64 + pc * 16);
            }
        }
    }

    float acc[4][4][4];
    #pragma unroll
    for (int i = 0; i < 4; i++)
        #pragma unroll
        for (int j = 0; j < 4; j++)
            #pragma unroll
            for (int q = 0; q < 4; q++) acc[i][j][q] = 0.f;

    const int KT = K >> 5;

    // prologue: stages 0 and 1, one commit group each
    #pragma unroll
    for (int s = 0; s < 2; s++) {
        if (s < KT) {
            const int k0 = s << 5;
            const uint32_t sOff = (uint32_t)(s * STAGE_BYTES);
            cp_async16(sA0 + sOff + ldOff0, &A[(size_t)(bM + ldR0     ) * K + k0 + ldC], true);
            cp_async16(sA0 + sOff + ldOff1, &A[(size_t)(bM + ldR0 + 64) * K + k0 + ldC], true);
            cp_async16(sB0 + sOff + ldOff0, &B[(size_t)(bN + ldR0     ) * K + k0 + ldC], (bN + ldR0     ) < N);
            cp_async16(sB0 + sOff + ldOff1, &B[(size_t)(bN + ldR0 + 64) * K + k0 + ldC], (bN + ldR0 + 64) < N);
        }
        cp_commit();
    }

    int stage = 0;
    for (int kt = 0; kt < KT; kt++) {
        cp_wait1();          // stage kt's group complete
        __syncthreads();     // visible to all; all threads done reading stage (kt-1)

        // issue stage kt+2 (overwrites buffer of stage kt-1)
        if (kt + 2 < KT) {
            const int ns = (stage + 2 >= 3) ? stage - 1 : stage + 2;
            const int k0 = (kt + 2) << 5;
            const uint32_t sOff = (uint32_t)(ns * STAGE_BYTES);
            cp_async16(sA0 + sOff + ldOff0, &A[(size_t)(bM + ldR0     ) * K + k0 + ldC], true);
            cp_async16(sA0 + sOff + ldOff1, &A[(size_t)(bM + ldR0 + 64) * K + k0 + ldC], true);
            cp_async16(sB0 + sOff + ldOff0, &B[(size_t)(bN + ldR0     ) * K + k0 + ldC], (bN + ldR0     ) < N);
            cp_async16(sB0 + sOff + ldOff1, &B[(size_t)(bN + ldR0 + 64) * K + k0 + ldC], (bN + ldR0 + 64) < N);
        }
        cp_commit();

        const uint32_t cOff = (uint32_t)(stage * STAGE_BYTES);
        #pragma unroll
        for (int kki = 0; kki < 2; kki++) {
            uint32_t fa[4][4], fb[2][4];
            #pragma unroll
            for (int mi = 0; mi < 4; mi++)
                ldsm_x4(fa[mi][0], fa[mi][1], fa[mi][2], fa[mi][3],
                        aAddr[mi][kki] + cOff);
            #pragma unroll
            for (int p = 0; p < 2; p++)
                ldsm_x4(fb[p][0], fb[p][1], fb[p][2], fb[p][3],
                        bAddr[p][kki] + cOff);
            #pragma unroll
            for (int mi = 0; mi < 4; mi++)
                #pragma unroll
                for (int p = 0; p < 2; p++)
                    #pragma unroll
                    for (int q = 0; q < 2; q++)
                        mma_bf16(acc[mi][p*2 + q], fa[mi],
                                 fb[p][2*q], fb[p][2*q + 1]);
        }
        stage = (stage + 1 >= 3) ? 0 : stage + 1;
    }

    // epilogue
    const int g = lane >> 2, tq = lane & 3;
    #pragma unroll
    for (int mi = 0; mi < 4; mi++) {
        #pragma unroll
        for (int ni = 0; ni < 4; ni++) {
            int row = bM + wRow*64 + mi*16 + g;
            int col = bN + wCol*32 + ni*8 + tq*2;
            if (col >= N) continue;
            float v0 = acc[mi][ni][0], v1 = acc[mi][ni][1];
            float v2 = acc[mi][ni][2], v3 = acc[mi][ni][3];
            if (EPI == 1) {
                float b0 = bias[col], b1 = bias[col+1];
                v0 = fmaxf(v0 + b0, 0.f); v1 = fmaxf(v1 + b1, 0.f);
                v2 = fmaxf(v2 + b0, 0.f); v3 = fmaxf(v3 + b1, 0.f);
            }
            if (EPI == 2) {
                float b0 = bias[col], b1 = bias[col+1];
                v0 = softplusf(v0 + b0); v1 = softplusf(v1 + b1);
                v2 = softplusf(v2 + b0); v3 = softplusf(v3 + b1);
            }
            if (EPI == 3) {
                const float2 r0 = *(const float2*)&res[(size_t)row * N + col];
                const float2 r1 = *(const float2*)&res[(size_t)(row+8) * N + col];
                v0 += r0.x; v1 += r0.y; v2 += r1.x; v3 += r1.y;
            }
            if (sizeof(OutT) == 4) {
                float2* o0 = (float2*)((float*)C + (size_t)row * N + col);
                float2* o1 = (float2*)((float*)C + (size_t)(row+8) * N + col);
                *o0 = make_float2(v0, v1);
                *o1 = make_float2(v2, v3);
            } else {
                *(__nv_bfloat162*)((bf16*)C + (size_t)row * N + col) =
                    __floats2bfloat162_rn(v0, v1);
                *(__nv_bfloat162*)((bf16*)C + (size_t)(row+8) * N + col) =
                    __floats2bfloat162_rn(v2, v3);
            }
        }
    }
}

// ---------------- depthwise conv (k=3, pad=1) + SiLU: 4 channels/thread -----
__global__ void conv_silu_kernel(const bf16* __restrict__ hin,
                                 const float* __restrict__ w,
                                 bf16* __restrict__ out) {
    size_t t = (size_t)blockIdx.x * blockDim.x + threadIdx.x;  // over MM*HH/4
    if (t >= (size_t)MM * HH / 4) return;
    int h4 = (int)(t & (HH/4 - 1));
    size_t row = t >> 8;
    int l = (int)(row & (LL - 1));
    int h = h4 * 4;
    float4 wv0 = *(const float4*)(w + h*3);
    float4 wv1 = *(const float4*)(w + h*3 + 4);
    float4 wv2 = *(const float4*)(w + h*3 + 8);
    const uint2* hp = (const uint2*)hin;
    uint2 zero = make_uint2(0u, 0u);
    uint2 m  = hp[t];
    uint2 lf = (l > 0)      ? hp[t - HH/4] : zero;
    uint2 rt = (l < LL - 1) ? hp[t + HH/4] : zero;
    float2 m0 = __bfloat1622float2(*(__nv_bfloat162*)&m.x);
    float2 m1 = __bfloat1622float2(*(__nv_bfloat162*)&m.y);
    float2 l0 = __bfloat1622float2(*(__nv_bfloat162*)&lf.x);
    float2 l1 = __bfloat1622float2(*(__nv_bfloat162*)&lf.y);
    float2 r0 = __bfloat1622float2(*(__nv_bfloat162*)&rt.x);
    float2 r1 = __bfloat1622float2(*(__nv_bfloat162*)&rt.y);
    float v0 = wv0.x*l0.x + wv0.y*m0.x + wv0.z*r0.x;
    float v1 = wv0.w*l0.y + wv1.x*m0.y + wv1.y*r0.y;
    float v2 = wv1.z*l1.x + wv1.w*m1.x + wv2.x*r1.x;
    float v3 = wv2.y*l1.y + wv2.z*m1.y + wv2.w*r1.y;
    v0 = v0 / (1.f + __expf(-v0));
    v1 = v1 / (1.f + __expf(-v1));
    v2 = v2 / (1.f + __expf(-v2));
    v3 = v3 / (1.f + __expf(-v3));
    uint2 o;
    *(__nv_bfloat162*)&o.x = __floats2bfloat162_rn(v0, v1);
    *(__nv_bfloat162*)&o.y = __floats2bfloat162_rn(v2, v3);
    ((uint2*)out)[t] = o;
}

// ---------------- selective scan: 8 lanes x 2 states per (b,h) --------------
// st = e*(st+w) - w with w = (1/A)*dt*x; 3-shuffle reduce over 8 lanes.
__global__ void scan_kernel(const bf16* __restrict__ xin,
                            const bf16* __restrict__ dt,
                            const float* __restrict__ Aw,
                            const float* __restrict__ Dw,
                            bf16* __restrict__ y) {
    int t = blockIdx.x * blockDim.x + threadIdx.x;  // < B*H*8 = 65536
    int n0 = t & 7;
    int hb = t >> 3;
    int h  = hb & (HH - 1);
    int b  = hb >> 10;

    float a0 = Aw[h * NS + n0];
    float a1 = Aw[h * NS + n0 + 8];
    float an0 = -expf(a0), an1 = -expf(a1);
    float al0 = an0 * 1.4426950408889634f;
    float al1 = an1 * 1.4426950408889634f;
    float iv0 = (fabsf(an0) < 1e-5f) ? 1.f : 1.f / an0;
    float iv1 = (fabsf(an1) < 1e-5f) ? 1.f : 1.f / an1;
    float d = Dw[h];
    bool writer = (n0 == 0);

    const bf16* xp = xin + (size_t)b * LL * HH + h;
    const bf16* dp = dt  + (size_t)b * LL * HH + h;
    bf16*       yp = y   + (size_t)b * LL * HH + h;

    float s0 = 0.f, s1 = 0.f;
    #pragma unroll 4
    for (int l = 0; l < LL; l++) {
        size_t off = (size_t)l * HH;
        float xt  = __bfloat162float(xp[off]);
        float dtt = __bfloat162float(dp[off]);
        float u = dtt * xt;
        float e0, e1;
        asm("ex2.approx.f32 %0, %1;" : "=f"(e0) : "f"(al0 * dtt));
        asm("ex2.approx.f32 %0, %1;" : "=f"(e1) : "f"(al1 * dtt));
        float w0 = iv0 * u, w1 = iv1 * u;
        s0 = fmaf(e0, s0 + w0, -w0);
        s1 = fmaf(e1, s1 + w1, -w1);
        float p = fmaf(s0, a0, s1 * a1);
        p += __shfl_xor_sync(0xffffffffu, p, 4);
        p += __shfl_xor_sync(0xffffffffu, p, 2);
        p += __shfl_xor_sync(0xffffffffu, p, 1);
        if (writer) yp[off] = __float2bfloat16(fmaf(d, xt, p));
    }
}

// ---------------- launch ----------------------------------------------------
extern "C" void kernel_launch(void* const* d_in, const int* in_sizes, int n_in,
                              void* d_out, int out_size) {
    const float* x      = (const float*)d_in[0];
    const float* ln_g   = (const float*)d_in[1];
    const float* ln_b   = (const float*)d_in[2];
    const float* W_in   = (const float*)d_in[3];
    const float* conv_w = (const float*)d_in[4];
    const float* A      = (const float*)d_in[5];
    const float* D      = (const float*)d_in[6];
    const float* dt_W1  = (const float*)d_in[7];
    const float* dt_b1  = (const float*)d_in[8];
    const float* dt_W2  = (const float*)d_in[9];
    const float* dt_b2  = (const float*)d_in[10];
    const float* W_out  = (const float*)d_in[11];
    float* out = (float*)d_out;

    bf16 *p_xn, *p_h, *p_hc, *p_dtr, *p_dt, *p_y;
    bf16 *p_win, *p_w1, *p_w2, *p_wout;
    cudaGetSymbolAddress((void**)&p_xn,  g_xn16);
    cudaGetSymbolAddress((void**)&p_h,   g_h16);
    cudaGetSymbolAddress((void**)&p_hc,  g_hc16);
    cudaGetSymbolAddress((void**)&p_dtr, g_dtr16);
    cudaGetSymbolAddress((void**)&p_dt,  g_dt16);
    cudaGetSymbolAddress((void**)&p_y,   g_y16);
    cudaGetSymbolAddress((void**)&p_win, g_win16);
    cudaGetSymbolAddress((void**)&p_w1,  g_w1_16);
    cudaGetSymbolAddress((void**)&p_w2,  g_w2_16);
    cudaGetSymbolAddress((void**)&p_wout,g_wout16);

    // 0) weight conversion f32 -> bf16 (merged, float4)
    f2bf4_kernel<<<(SEG3/4 + 255)/256, 256>>>(W_in, dt_W1, dt_W2, W_out,
                                              p_win, p_w1, p_w2, p_wout);

    // 1) LayerNorm (f32 in, bf16 out)
    ln_kernel<<<MM, 128>>>(x, ln_g, ln_b, p_xn);

    // 2) in_proj: h = xn @ W_in^T   [16384,512] x [1024,512]^T
    gemm_bf16<0, bf16><<<dim3(HH/128, MM/128), 256>>>(
        p_xn, p_win, nullptr, nullptr, p_h, MM, HH, DIN);

    // 3) depthwise conv + SiLU (4 channels/thread)
    conv_silu_kernel<<<(MM * HH / 4) / 256, 256>>>(p_h, conv_w, p_hc);

    // 4) dt hidden: relu(hc @ dt_W1^T + b1)   N=64
    gemm_bf16<1, bf16><<<dim3(1, MM/128), 256>>>(
        p_hc, p_w1, dt_b1, nullptr, p_dtr, MM, RR, HH);

    // 5) dt: softplus(dtr @ dt_W2^T + b2)
    gemm_bf16<2, bf16><<<dim3(HH/128, MM/128), 256>>>(
        p_dtr, p_w2, dt_b2, nullptr, p_dt, MM, HH, RR);

    // 6) selective scan (8 lanes x 2 states)
    scan_kernel<<<(BB * HH * 8) / 256, 256>>>(p_hc, p_dt, A, D, p_y);

    // 7) out proj + residual: out = y @ W_out^T + x
    gemm_bf16<3, float><<<dim3(DIN/128, MM/128), 256>>>(
        p_y, p_wout, nullptr, x, out, MM, DIN, HH);
}

// round 12
// speedup vs baseline: 1.1277x; 1.1277x over previous
#include <cuda_runtime.h>
#include <cuda_bf16.h>
#include <cstdint>
#include <math.h>

// Problem dims (fixed by reference)
#define BB 8
#define LL 2048
#define DIN 512
#define HH 1024
#define NS 16
#define RR 64
#define MM (BB * LL)   // 16384

typedef __nv_bfloat16 bf16;

// ---------------- scratch (device globals; no allocation allowed) ----------
__device__ bf16  g_xn16 [(size_t)MM * DIN];
__device__ bf16  g_h16  [(size_t)MM * HH];
__device__ bf16  g_hc16 [(size_t)MM * HH];
__device__ bf16  g_dtr16[(size_t)MM * RR];
__device__ bf16  g_dt16 [(size_t)MM * HH];
__device__ bf16  g_y16  [(size_t)MM * HH];
__device__ bf16  g_win16 [(size_t)HH * DIN];
__device__ bf16  g_w1_16 [(size_t)RR * HH];
__device__ bf16  g_w2_16 [(size_t)HH * RR];
__device__ bf16  g_wout16[(size_t)DIN * HH];

// ---------------- helpers ---------------------------------------------------
__device__ __forceinline__ float blockReduce128(float v, float* sh) {
    #pragma unroll
    for (int o = 16; o > 0; o >>= 1) v += __shfl_xor_sync(0xffffffffu, v, o);
    int w = threadIdx.x >> 5;
    if ((threadIdx.x & 31) == 0) sh[w] = v;
    __syncthreads();
    float r = sh[0] + sh[1] + sh[2] + sh[3];
    __syncthreads();
    return r;
}

__device__ __forceinline__ float softplusf(float v) {
    return (v > 20.f) ? v : log1pf(expf(v));
}

__device__ __forceinline__ void cp_async16(uint32_t saddr, const void* gptr, bool pred) {
    int sz = pred ? 16 : 0;
    asm volatile("cp.async.cg.shared.global [%0], [%1], 16, %2;\n"
                 :: "r"(saddr), "l"(gptr), "r"(sz));
}
__device__ __forceinline__ void cp_commit() {
    asm volatile("cp.async.commit_group;\n" ::: "memory");
}
__device__ __forceinline__ void cp_wait1() {
    asm volatile("cp.async.wait_group 1;\n" ::: "memory");
}

// ---------------- merged f32 -> bf16 weight conversion ----------------------
#define SEG0 (HH*DIN)                 // 524288
#define SEG1 (SEG0 + RR*HH)           // 589824
#define SEG2 (SEG1 + HH*RR)           // 655360
#define SEG3 (SEG2 + DIN*HH)          // 1179648
__global__ void f2bf4_kernel(const float* __restrict__ s0, const float* __restrict__ s1,
                             const float* __restrict__ s2, const float* __restrict__ s3,
                             bf16* __restrict__ d0, bf16* __restrict__ d1,
                             bf16* __restrict__ d2, bf16* __restrict__ d3) {
    int i = (blockIdx.x * blockDim.x + threadIdx.x) * 4;
    if (i >= SEG3) return;
    const float* s; bf16* d; int off;
    if      (i < SEG0) { s = s0; d = d0; off = i; }
    else if (i < SEG1) { s = s1; d = d1; off = i - SEG0; }
    else if (i < SEG2) { s = s2; d = d2; off = i - SEG1; }
    else               { s = s3; d = d3; off = i - SEG2; }
    float4 v = *(const float4*)(s + off);
    __nv_bfloat162* o = (__nv_bfloat162*)(d + off);
    o[0] = __floats2bfloat162_rn(v.x, v.y);
    o[1] = __floats2bfloat162_rn(v.z, v.w);
}

// ---------------- LayerNorm: one block (128 thr) per row of 512 -------------
__global__ void ln_kernel(const float* __restrict__ x,
                          const float* __restrict__ gamma,
                          const float* __restrict__ beta,
                          bf16* __restrict__ out) {
    __shared__ float sh[4];
    size_t row = blockIdx.x;
    const float4* xr = (const float4*)(x + row * DIN);
    float4 v = xr[threadIdx.x];
    float s = blockReduce128(v.x + v.y + v.z + v.w, sh);
    float mu = s * (1.f / DIN);
    float dx = v.x - mu, dy = v.y - mu, dz = v.z - mu, dw = v.w - mu;
    float s2 = blockReduce128(dx*dx + dy*dy + dz*dz + dw*dw, sh);
    float rstd = rsqrtf(s2 * (1.f / DIN) + 1e-5f);
    float4 gv = ((const float4*)gamma)[threadIdx.x];
    float4 bv = ((const float4*)beta )[threadIdx.x];
    __nv_bfloat162* orow = (__nv_bfloat162*)(out + row * DIN);
    orow[2*threadIdx.x + 0] = __floats2bfloat162_rn(dx * rstd * gv.x + bv.x,
                                                    dy * rstd * gv.y + bv.y);
    orow[2*threadIdx.x + 1] = __floats2bfloat162_rn(dz * rstd * gv.z + bv.z,
                                                    dw * rstd * gv.w + bv.w);
}

// ---------------- MMA primitives --------------------------------------------
__device__ __forceinline__ void ldsm_x4(uint32_t& r0, uint32_t& r1,
                                        uint32_t& r2, uint32_t& r3,
                                        uint32_t addr) {
    asm volatile("ldmatrix.sync.aligned.m8n8.x4.shared.b16 {%0,%1,%2,%3}, [%4];"
                 : "=r"(r0), "=r"(r1), "=r"(r2), "=r"(r3) : "r"(addr));
}

__device__ __forceinline__ void mma_bf16(float* c4, const uint32_t* af,
                                         uint32_t b0, uint32_t b1) {
    asm volatile(
        "mma.sync.aligned.m16n8k16.row.col.f32.bf16.bf16.f32 "
        "{%0,%1,%2,%3}, {%4,%5,%6,%7}, {%8,%9}, {%0,%1,%2,%3};"
        : "+f"(c4[0]), "+f"(c4[1]), "+f"(c4[2]), "+f"(c4[3])
        : "r"(af[0]), "r"(af[1]), "r"(af[2]), "r"(af[3]), "r"(b0), "r"(b1));
}

// ---------------- bf16 tensor-core GEMM: C[M,N] = A[M,K] * B[N,K]^T ---------
// 128x128 tile, BK=32, 3-stage cp.async pipeline, one __syncthreads per k-tile.
// Unpadded 64B rows + XOR chunk swizzle: physical_chunk = chunk ^ ((row>>1)&3).
// Static smem 49152 B (validated correct in round 9).
// EPI: 0 = none (bf16 out), 1 = bias+ReLU (bf16), 2 = bias+softplus (bf16),
//      3 = +residual (f32 out)
#define STAGE_BYTES 8192    // 128 rows * 64 bytes
template <int EPI, typename OutT>
__global__ __launch_bounds__(256)
void gemm_bf16(const bf16* __restrict__ A, const bf16* __restrict__ B,
               const float* __restrict__ bias, const float* __restrict__ res,
               OutT* __restrict__ C, int M, int N, int K) {
    __shared__ bf16 smemAll[3 * 2 * 4096];   // 49152 B: A stages 0-2, then B stages 0-2

    const int tid  = threadIdx.x;
    const int lane = tid & 31;
    const int wid  = tid >> 5;
    const int wRow = wid >> 2;      // 0..1
    const int wCol = wid & 3;       // 0..3
    const int bM = blockIdx.y * 128;
    const int bN = blockIdx.x * 128;

    const uint32_t sA0 = (uint32_t)__cvta_generic_to_shared(smemAll);
    const uint32_t sB0 = sA0 + 3 * STAGE_BYTES;

    // staging: thread writes rows (tid>>2) and (tid>>2)+64, chunk tid&3 (swizzled)
    const int ldR0 = tid >> 2;
    const int ldC  = (tid & 3) * 8;                 // gmem half offset
    const int ldPC = (tid & 3) ^ ((ldR0 >> 1) & 3); // physical chunk (same for +64)
    const uint32_t ldOff0 = (uint32_t)(ldR0 * 64 + ldPC * 16);
    const uint32_t ldOff1 = ldOff0 + 64 * 64;

    // ldmatrix lane addresses, precomputed per (tile, kk-half): XOR swizzle
    uint32_t aAddr[4][2], bAddr[2][2];
    {
        const int ar = lane & 15, cbA = lane >> 4;
        #pragma unroll
        for (int mi = 0; mi < 4; mi++) {
            int row = wRow*64 + mi*16 + ar;
            int sw = (row >> 1) & 3;
            #pragma unroll
            for (int kki = 0; kki < 2; kki++) {
                int pc = (cbA + kki*2) ^ sw;
                aAddr[mi][kki] = sA0 + (uint32_t)(row * 64 + pc * 16);
            }
        }
        const int br = ((lane >> 4) << 3) + (lane & 7);
        const int cbB = (lane >> 3) & 1;
        #pragma unroll
        for (int p = 0; p < 2; p++) {
            int row = wCol*32 + p*16 + br;
            int sw = (row >> 1) & 3;
            #pragma unroll
            for (int kki = 0; kki < 2; kki++) {
                int pc = (cbB + kki*2) ^ sw;
                bAddr[p][kki] = sB0 + (uint32_t)(row * 64 + pc * 16);
            }
        }
    }

    float acc[4][4][4];
    #pragma unroll
    for (int i = 0; i < 4; i++)
        #pragma unroll
        for (int j = 0; j < 4; j++)
            #pragma unroll
            for (int q = 0; q < 4; q++) acc[i][j][q] = 0.f;

    const int KT = K >> 5;

    // prologue: stages 0 and 1, one commit group each
    #pragma unroll
    for (int s = 0; s < 2; s++) {
        if (s < KT) {
            const int k0 = s << 5;
            const uint32_t sOff = (uint32_t)(s * STAGE_BYTES);
            cp_async16(sA0 + sOff + ldOff0, &A[(size_t)(bM + ldR0     ) * K + k0 + ldC], true);
            cp_async16(sA0 + sOff + ldOff1, &A[(size_t)(bM + ldR0 + 64) * K + k0 + ldC], true);
            cp_async16(sB0 + sOff + ldOff0, &B[(size_t)(bN + ldR0     ) * K + k0 + ldC], (bN + ldR0     ) < N);
            cp_async16(sB0 + sOff + ldOff1, &B[(size_t)(bN + ldR0 + 64) * K + k0 + ldC], (bN + ldR0 + 64) < N);
        }
        cp_commit();
    }

    int stage = 0;
    for (int kt = 0; kt < KT; kt++) {
        cp_wait1();          // stage kt's group complete (in-order groups)
        __syncthreads();     // all threads done reading stage (kt-1)

        // issue stage kt+2 (overwrites buffer of stage kt-1)
        if (kt + 2 < KT) {
            const int ns = (stage + 2 >= 3) ? stage - 1 : stage + 2;
            const int k0 = (kt + 2) << 5;
            const uint32_t sOff = (uint32_t)(ns * STAGE_BYTES);
            cp_async16(sA0 + sOff + ldOff0, &A[(size_t)(bM + ldR0     ) * K + k0 + ldC], true);
            cp_async16(sA0 + sOff + ldOff1, &A[(size_t)(bM + ldR0 + 64) * K + k0 + ldC], true);
            cp_async16(sB0 + sOff + ldOff0, &B[(size_t)(bN + ldR0     ) * K + k0 + ldC], (bN + ldR0     ) < N);
            cp_async16(sB0 + sOff + ldOff1, &B[(size_t)(bN + ldR0 + 64) * K + k0 + ldC], (bN + ldR0 + 64) < N);
        }
        cp_commit();

        const uint32_t cOff = (uint32_t)(stage * STAGE_BYTES);
        #pragma unroll
        for (int kki = 0; kki < 2; kki++) {
            uint32_t fa[4][4], fb[2][4];
            #pragma unroll
            for (int mi = 0; mi < 4; mi++)
                ldsm_x4(fa[mi][0], fa[mi][1], fa[mi][2], fa[mi][3],
                        aAddr[mi][kki] + cOff);
            #pragma unroll
            for (int p = 0; p < 2; p++)
                ldsm_x4(fb[p][0], fb[p][1], fb[p][2], fb[p][3],
                        bAddr[p][kki] + cOff);
            #pragma unroll
            for (int mi = 0; mi < 4; mi++)
                #pragma unroll
                for (int p = 0; p < 2; p++)
                    #pragma unroll
                    for (int q = 0; q < 2; q++)
                        mma_bf16(acc[mi][p*2 + q], fa[mi],
                                 fb[p][2*q], fb[p][2*q + 1]);
        }
        stage = (stage + 1 >= 3) ? 0 : stage + 1;
    }

    // epilogue
    const int g = lane >> 2, tq = lane & 3;
    #pragma unroll
    for (int mi = 0; mi < 4; mi++) {
        #pragma unroll
        for (int ni = 0; ni < 4; ni++) {
            int row = bM + wRow*64 + mi*16 + g;
            int col = bN + wCol*32 + ni*8 + tq*2;
            if (col >= N) continue;
            float v0 = acc[mi][ni][0], v1 = acc[mi][ni][1];
            float v2 = acc[mi][ni][2], v3 = acc[mi][ni][3];
            if (EPI == 1) {
                float b0 = bias[col], b1 = bias[col+1];
                v0 = fmaxf(v0 + b0, 0.f); v1 = fmaxf(v1 + b1, 0.f);
                v2 = fmaxf(v2 + b0, 0.f); v3 = fmaxf(v3 + b1, 0.f);
            }
            if (EPI == 2) {
                float b0 = bias[col], b1 = bias[col+1];
                v0 = softplusf(v0 + b0); v1 = softplusf(v1 + b1);
                v2 = softplusf(v2 + b0); v3 = softplusf(v3 + b1);
            }
            if (EPI == 3) {
                const float2 r0 = *(const float2*)&res[(size_t)row * N + col];
                const float2 r1 = *(const float2*)&res[(size_t)(row+8) * N + col];
                v0 += r0.x; v1 += r0.y; v2 += r1.x; v3 += r1.y;
            }
            if (sizeof(OutT) == 4) {
                float2* o0 = (float2*)((float*)C + (size_t)row * N + col);
                float2* o1 = (float2*)((float*)C + (size_t)(row+8) * N + col);
                *o0 = make_float2(v0, v1);
                *o1 = make_float2(v2, v3);
            } else {
                *(__nv_bfloat162*)((bf16*)C + (size_t)row * N + col) =
                    __floats2bfloat162_rn(v0, v1);
                *(__nv_bfloat162*)((bf16*)C + (size_t)(row+8) * N + col) =
                    __floats2bfloat162_rn(v2, v3);
            }
        }
    }
}

// ---------------- depthwise conv (k=3, pad=1) + SiLU: 4 channels/thread -----
__global__ void conv_silu_kernel(const bf16* __restrict__ hin,
                                 const float* __restrict__ w,
                                 bf16* __restrict__ out) {
    size_t t = (size_t)blockIdx.x * blockDim.x + threadIdx.x;  // over MM*HH/4
    if (t >= (size_t)MM * HH / 4) return;
    int h4 = (int)(t & (HH/4 - 1));
    size_t row = t >> 8;
    int l = (int)(row & (LL - 1));
    int h = h4 * 4;
    float4 wv0 = *(const float4*)(w + h*3);
    float4 wv1 = *(const float4*)(w + h*3 + 4);
    float4 wv2 = *(const float4*)(w + h*3 + 8);
    const uint2* hp = (const uint2*)hin;
    uint2 zero = make_uint2(0u, 0u);
    uint2 m  = hp[t];
    uint2 lf = (l > 0)      ? hp[t - HH/4] : zero;
    uint2 rt = (l < LL - 1) ? hp[t + HH/4] : zero;
    float2 m0 = __bfloat1622float2(*(__nv_bfloat162*)&m.x);
    float2 m1 = __bfloat1622float2(*(__nv_bfloat162*)&m.y);
    float2 l0 = __bfloat1622float2(*(__nv_bfloat162*)&lf.x);
    float2 l1 = __bfloat1622float2(*(__nv_bfloat162*)&lf.y);
    float2 r0 = __bfloat1622float2(*(__nv_bfloat162*)&rt.x);
    float2 r1 = __bfloat1622float2(*(__nv_bfloat162*)&rt.y);
    float v0 = wv0.x*l0.x + wv0.y*m0.x + wv0.z*r0.x;
    float v1 = wv0.w*l0.y + wv1.x*m0.y + wv1.y*r0.y;
    float v2 = wv1.z*l1.x + wv1.w*m1.x + wv2.x*r1.x;
    float v3 = wv2.y*l1.y + wv2.z*m1.y + wv2.w*r1.y;
    v0 = v0 / (1.f + __expf(-v0));
    v1 = v1 / (1.f + __expf(-v1));
    v2 = v2 / (1.f + __expf(-v2));
    v3 = v3 / (1.f + __expf(-v3));
    uint2 o;
    *(__nv_bfloat162*)&o.x = __floats2bfloat162_rn(v0, v1);
    *(__nv_bfloat162*)&o.y = __floats2bfloat162_rn(v2, v3);
    ((uint2*)out)[t] = o;
}

// ---------------- selective scan: thread per (b, h, n) [R4 proven - FINAL] --
__global__ void scan_kernel(const bf16* __restrict__ xin,
                            const bf16* __restrict__ dt,
                            const float* __restrict__ Aw,
                            const float* __restrict__ Dw,
                            bf16* __restrict__ y) {
    int t = blockIdx.x * blockDim.x + threadIdx.x;  // < B*H*NS = 131072
    int n  = t & (NS - 1);
    int hb = t >> 4;
    int h  = hb & (HH - 1);
    int b  = hb >> 10;

    float a    = Aw[h * NS + n];
    float aneg = -expf(a);
    float inva = (fabsf(aneg) < 1e-5f) ? 1.f : 1.f / aneg;
    float d    = Dw[h];

    const bf16* xp = xin + (size_t)b * LL * HH + h;
    const bf16* dp = dt  + (size_t)b * LL * HH + h;
    bf16*       yp = y   + (size_t)b * LL * HH + h;

    float state = 0.f;
    for (int l = 0; l < LL; l++) {
        size_t off = (size_t)l * HH;
        float xt  = __bfloat162float(xp[off]);
        float dtt = __bfloat162float(dp[off]);
        float e   = __expf(aneg * dtt);
        float db  = (e - 1.f) * inva * dtt;
        state = fmaf(e, state, db * xt);
        float p = state * a;
        p += __shfl_xor_sync(0xffffffffu, p, 8);
        p += __shfl_xor_sync(0xffffffffu, p, 4);
        p += __shfl_xor_sync(0xffffffffu, p, 2);
        p += __shfl_xor_sync(0xffffffffu, p, 1);
        if (n == 0) yp[off] = __float2bfloat16(fmaf(d, xt, p));
    }
}

// ---------------- launch ----------------------------------------------------
extern "C" void kernel_launch(void* const* d_in, const int* in_sizes, int n_in,
                              void* d_out, int out_size) {
    const float* x      = (const float*)d_in[0];
    const float* ln_g   = (const float*)d_in[1];
    const float* ln_b   = (const float*)d_in[2];
    const float* W_in   = (const float*)d_in[3];
    const float* conv_w = (const float*)d_in[4];
    const float* A      = (const float*)d_in[5];
    const float* D      = (const float*)d_in[6];
    const float* dt_W1  = (const float*)d_in[7];
    const float* dt_b1  = (const float*)d_in[8];
    const float* dt_W2  = (const float*)d_in[9];
    const float* dt_b2  = (const float*)d_in[10];
    const float* W_out  = (const float*)d_in[11];
    float* out = (float*)d_out;

    bf16 *p_xn, *p_h, *p_hc, *p_dtr, *p_dt, *p_y;
    bf16 *p_win, *p_w1, *p_w2, *p_wout;
    cudaGetSymbolAddress((void**)&p_xn,  g_xn16);
    cudaGetSymbolAddress((void**)&p_h,   g_h16);
    cudaGetSymbolAddress((void**)&p_hc,  g_hc16);
    cudaGetSymbolAddress((void**)&p_dtr, g_dtr16);
    cudaGetSymbolAddress((void**)&p_dt,  g_dt16);
    cudaGetSymbolAddress((void**)&p_y,   g_y16);
    cudaGetSymbolAddress((void**)&p_win, g_win16);
    cudaGetSymbolAddress((void**)&p_w1,  g_w1_16);
    cudaGetSymbolAddress((void**)&p_w2,  g_w2_16);
    cudaGetSymbolAddress((void**)&p_wout,g_wout16);

    // 0) weight conversion f32 -> bf16 (merged, float4)
    f2bf4_kernel<<<(SEG3/4 + 255)/256, 256>>>(W_in, dt_W1, dt_W2, W_out,
                                              p_win, p_w1, p_w2, p_wout);

    // 1) LayerNorm (f32 in, bf16 out)
    ln_kernel<<<MM, 128>>>(x, ln_g, ln_b, p_xn);

    // 2) in_proj: h = xn @ W_in^T   [16384,512] x [1024,512]^T
    gemm_bf16<0, bf16><<<dim3(HH/128, MM/128), 256>>>(
        p_xn, p_win, nullptr, nullptr, p_h, MM, HH, DIN);

    // 3) depthwise conv + SiLU (4 channels/thread)
    conv_silu_kernel<<<(MM * HH / 4) / 256, 256>>>(p_h, conv_w, p_hc);

    // 4) dt hidden: relu(hc @ dt_W1^T + b1)   N=64
    gemm_bf16<1, bf16><<<dim3(1, MM/128), 256>>>(
        p_hc, p_w1, dt_b1, nullptr, p_dtr, MM, RR, HH);

    // 5) dt: softplus(dtr @ dt_W2^T + b2)
    gemm_bf16<2, bf16><<<dim3(HH/128, MM/128), 256>>>(
        p_dtr, p_w2, dt_b2, nullptr, p_dt, MM, HH, RR);

    // 6) selective scan (R4 proven: 1 thread per (b,h,n))
    scan_kernel<<<(BB * HH * NS) / 256, 256>>>(p_hc, p_dt, A, D, p_y);

    // 7) out proj + residual: out = y @ W_out^T + x
    gemm_bf16<3, float><<<dim3(DIN/128, MM/128), 256>>>(
        p_y, p_wout, nullptr, x, out, MM, DIN, HH);
}

// round 15
// speedup vs baseline: 1.1428x; 1.0134x over previous
#include <cuda_runtime.h>
#include <cuda_bf16.h>
#include <cstdint>
#include <math.h>

// Problem dims (fixed by reference)
#define BB 8
#define LL 2048
#define DIN 512
#define HH 1024
#define NS 16
#define RR 64
#define MM (BB * LL)   // 16384

typedef __nv_bfloat16 bf16;

// ---------------- scratch (device globals; no allocation allowed) ----------
__device__ bf16  g_xn16 [(size_t)MM * DIN];
__device__ bf16  g_h16  [(size_t)MM * HH];
__device__ bf16  g_hc16 [(size_t)MM * HH];
__device__ bf16  g_dtr16[(size_t)MM * RR];
__device__ bf16  g_dt16 [(size_t)MM * HH];
__device__ bf16  g_y16  [(size_t)MM * HH];
__device__ bf16  g_win16 [(size_t)HH * DIN];
__device__ bf16  g_w1_16 [(size_t)RR * HH];
__device__ bf16  g_w2_16 [(size_t)HH * RR];
__device__ bf16  g_wout16[(size_t)DIN * HH];

// ---------------- helpers ---------------------------------------------------
__device__ __forceinline__ float blockReduce128(float v, float* sh) {
    #pragma unroll
    for (int o = 16; o > 0; o >>= 1) v += __shfl_xor_sync(0xffffffffu, v, o);
    int w = threadIdx.x >> 5;
    if ((threadIdx.x & 31) == 0) sh[w] = v;
    __syncthreads();
    float r = sh[0] + sh[1] + sh[2] + sh[3];
    __syncthreads();
    return r;
}

__device__ __forceinline__ float softplusf(float v) {
    return (v > 20.f) ? v : log1pf(expf(v));
}

__device__ __forceinline__ void cp_async16(uint32_t saddr, const void* gptr, bool pred) {
    int sz = pred ? 16 : 0;
    asm volatile("cp.async.cg.shared.global [%0], [%1], 16, %2;\n"
                 :: "r"(saddr), "l"(gptr), "r"(sz));
}
__device__ __forceinline__ void cp_commit() {
    asm volatile("cp.async.commit_group;\n" ::: "memory");
}
__device__ __forceinline__ void cp_wait1() {
    asm volatile("cp.async.wait_group 1;\n" ::: "memory");
}

// ---------------- merged f32 -> bf16 weight conversion ----------------------
#define SEG0 (HH*DIN)                 // 524288
#define SEG1 (SEG0 + RR*HH)           // 589824
#define SEG2 (SEG1 + HH*RR)           // 655360
#define SEG3 (SEG2 + DIN*HH)          // 1179648
__global__ void f2bf4_kernel(const float* __restrict__ s0, const float* __restrict__ s1,
                             const float* __restrict__ s2, const float* __restrict__ s3,
                             bf16* __restrict__ d0, bf16* __restrict__ d1,
                             bf16* __restrict__ d2, bf16* __restrict__ d3) {
    int i = (blockIdx.x * blockDim.x + threadIdx.x) * 4;
    if (i >= SEG3) return;
    const float* s; bf16* d; int off;
    if      (i < SEG0) { s = s0; d = d0; off = i; }
    else if (i < SEG1) { s = s1; d = d1; off = i - SEG0; }
    else if (i < SEG2) { s = s2; d = d2; off = i - SEG1; }
    else               { s = s3; d = d3; off = i - SEG2; }
    float4 v = *(const float4*)(s + off);
    __nv_bfloat162* o = (__nv_bfloat162*)(d + off);
    o[0] = __floats2bfloat162_rn(v.x, v.y);
    o[1] = __floats2bfloat162_rn(v.z, v.w);
}

// ---------------- LayerNorm: one block (128 thr) per row of 512 -------------
__global__ void ln_kernel(const float* __restrict__ x,
                          const float* __restrict__ gamma,
                          const float* __restrict__ beta,
                          bf16* __restrict__ out) {
    __shared__ float sh[4];
    size_t row = blockIdx.x;
    const float4* xr = (const float4*)(x + row * DIN);
    float4 v = xr[threadIdx.x];
    float s = blockReduce128(v.x + v.y + v.z + v.w, sh);
    float mu = s * (1.f / DIN);
    float dx = v.x - mu, dy = v.y - mu, dz = v.z - mu, dw = v.w - mu;
    float s2 = blockReduce128(dx*dx + dy*dy + dz*dz + dw*dw, sh);
    float rstd = rsqrtf(s2 * (1.f / DIN) + 1e-5f);
    float4 gv = ((const float4*)gamma)[threadIdx.x];
    float4 bv = ((const float4*)beta )[threadIdx.x];
    __nv_bfloat162* orow = (__nv_bfloat162*)(out + row * DIN);
    orow[2*threadIdx.x + 0] = __floats2bfloat162_rn(dx * rstd * gv.x + bv.x,
                                                    dy * rstd * gv.y + bv.y);
    orow[2*threadIdx.x + 1] = __floats2bfloat162_rn(dz * rstd * gv.z + bv.z,
                                                    dw * rstd * gv.w + bv.w);
}

// ---------------- MMA primitives --------------------------------------------
__device__ __forceinline__ void ldsm_x4(uint32_t& r0, uint32_t& r1,
                                        uint32_t& r2, uint32_t& r3,
                                        uint32_t addr) {
    asm volatile("ldmatrix.sync.aligned.m8n8.x4.shared.b16 {%0,%1,%2,%3}, [%4];"
                 : "=r"(r0), "=r"(r1), "=r"(r2), "=r"(r3) : "r"(addr));
}

__device__ __forceinline__ void mma_bf16(float* c4, const uint32_t* af,
                                         uint32_t b0, uint32_t b1) {
    asm volatile(
        "mma.sync.aligned.m16n8k16.row.col.f32.bf16.bf16.f32 "
        "{%0,%1,%2,%3}, {%4,%5,%6,%7}, {%8,%9}, {%0,%1,%2,%3};"
        : "+f"(c4[0]), "+f"(c4[1]), "+f"(c4[2]), "+f"(c4[3])
        : "r"(af[0]), "r"(af[1]), "r"(af[2]), "r"(af[3]), "r"(b0), "r"(b1));
}

// ---------------- bf16 mma.sync GEMM: C[M,N] = A[M,K] * B[N,K]^T ------------
// 128 x (PB*64) tile, BK=32, 3-stage cp.async, XOR chunk swizzle, static smem.
// PB=2: BN=128 (warp n-slab 32); PB=1: BN=64 (warp n-slab 16, half the MMAs).
// EPI: 0 = none (bf16 out), 1 = bias+ReLU (bf16), 2 = bias+softplus (bf16),
//      3 = +residual (f32 out)
#define STAGE_BYTES 8192    // 128 rows * 64 bytes
template <int EPI, int PB, typename OutT>
__global__ __launch_bounds__(256)
void gemm_bf16(const bf16* __restrict__ A, const bf16* __restrict__ B,
               const float* __restrict__ bias, const float* __restrict__ res,
               OutT* __restrict__ C, int M, int N, int K) {
    __shared__ bf16 smemAll[3 * 2 * 4096];   // 49152 B

    const int tid  = threadIdx.x;
    const int lane = tid & 31;
    const int wid  = tid >> 5;
    const int wRow = wid >> 2;
    const int wCol = wid & 3;
    const int NW   = PB * 16;            // warp n-slab width
    const int bM = blockIdx.y * 128;
    const int bN = blockIdx.x * (PB * 64);

    const uint32_t sA0 = (uint32_t)__cvta_generic_to_shared(smemAll);
    const uint32_t sB0 = sA0 + 3 * STAGE_BYTES;

    const int ldR0 = tid >> 2;
    const int ldC  = (tid & 3) * 8;
    const int ldPC = (tid & 3) ^ ((ldR0 >> 1) & 3);
    const uint32_t ldOff0 = (uint32_t)(ldR0 * 64 + ldPC * 16);
    const uint32_t ldOff1 = ldOff0 + 64 * 64;

    uint32_t aAddr[4][2], bAddr[PB][2];
    {
        const int ar = lane & 15, cbA = lane >> 4;
        #pragma unroll
        for (int mi = 0; mi < 4; mi++) {
            int row = wRow*64 + mi*16 + ar;
            int sw = (row >> 1) & 3;
            #pragma unroll
            for (int kki = 0; kki < 2; kki++) {
                int pc = (cbA + kki*2) ^ sw;
                aAddr[mi][kki] = sA0 + (uint32_t)(row * 64 + pc * 16);
            }
        }
        const int br = ((lane >> 4) << 3) + (lane & 7);
        const int cbB = (lane >> 3) & 1;
        #pragma unroll
        for (int p = 0; p < PB; p++) {
            int row = wCol*NW + p*16 + br;
            int sw = (row >> 1) & 3;
            #pragma unroll
            for (int kki = 0; kki < 2; kki++) {
                int pc = (cbB + kki*2) ^ sw;
                bAddr[p][kki] = sB0 + (uint32_t)(row * 64 + pc * 16);
            }
        }
    }

    float acc[4][2*PB][4];
    #pragma unroll
    for (int i = 0; i < 4; i++)
        #pragma unroll
        for (int j = 0; j < 2*PB; j++)
            #pragma unroll
            for (int q = 0; q < 4; q++) acc[i][j][q] = 0.f;

    const int KT = K >> 5;

    #pragma unroll
    for (int s = 0; s < 2; s++) {
        if (s < KT) {
            const int k0 = s << 5;
            const uint32_t sOff = (uint32_t)(s * STAGE_BYTES);
            cp_async16(sA0 + sOff + ldOff0, &A[(size_t)(bM + ldR0     ) * K + k0 + ldC], true);
            cp_async16(sA0 + sOff + ldOff1, &A[(size_t)(bM + ldR0 + 64) * K + k0 + ldC], true);
            cp_async16(sB0 + sOff + ldOff0, &B[(size_t)(bN + ldR0     ) * K + k0 + ldC], (bN + ldR0     ) < N);
            cp_async16(sB0 + sOff + ldOff1, &B[(size_t)(bN + ldR0 + 64) * K + k0 + ldC], (bN + ldR0 + 64) < N);
        }
        cp_commit();
    }

    int stage = 0;
    for (int kt = 0; kt < KT; kt++) {
        cp_wait1();
        __syncthreads();

        if (kt + 2 < KT) {
            const int ns = (stage + 2 >= 3) ? stage - 1 : stage + 2;
            const int k0 = (kt + 2) << 5;
            const uint32_t sOff = (uint32_t)(ns * STAGE_BYTES);
            cp_async16(sA0 + sOff + ldOff0, &A[(size_t)(bM + ldR0     ) * K + k0 + ldC], true);
            cp_async16(sA0 + sOff + ldOff1, &A[(size_t)(bM + ldR0 + 64) * K + k0 + ldC], true);
            cp_async16(sB0 + sOff + ldOff0, &B[(size_t)(bN + ldR0     ) * K + k0 + ldC], (bN + ldR0     ) < N);
            cp_async16(sB0 + sOff + ldOff1, &B[(size_t)(bN + ldR0 + 64) * K + k0 + ldC], (bN + ldR0 + 64) < N);
        }
        cp_commit();

        const uint32_t cOff = (uint32_t)(stage * STAGE_BYTES);
        #pragma unroll
        for (int kki = 0; kki < 2; kki++) {
            uint32_t fa[4][4], fb[PB][4];
            #pragma unroll
            for (int mi = 0; mi < 4; mi++)
                ldsm_x4(fa[mi][0], fa[mi][1], fa[mi][2], fa[mi][3],
                        aAddr[mi][kki] + cOff);
            #pragma unroll
            for (int p = 0; p < PB; p++)
                ldsm_x4(fb[p][0], fb[p][1], fb[p][2], fb[p][3],
                        bAddr[p][kki] + cOff);
            #pragma unroll
            for (int mi = 0; mi < 4; mi++)
                #pragma unroll
                for (int p = 0; p < PB; p++)
                    #pragma unroll
                    for (int q = 0; q < 2; q++)
                        mma_bf16(acc[mi][p*2 + q], fa[mi],
                                 fb[p][2*q], fb[p][2*q + 1]);
        }
        stage = (stage + 1 >= 3) ? 0 : stage + 1;
    }

    const int g = lane >> 2, tq = lane & 3;
    #pragma unroll
    for (int mi = 0; mi < 4; mi++) {
        #pragma unroll
        for (int ni = 0; ni < 2*PB; ni++) {
            int row = bM + wRow*64 + mi*16 + g;
            int col = bN + wCol*NW + ni*8 + tq*2;
            if (col >= N) continue;
            float v0 = acc[mi][ni][0], v1 = acc[mi][ni][1];
            float v2 = acc[mi][ni][2], v3 = acc[mi][ni][3];
            if (EPI == 1) {
                float b0 = bias[col], b1 = bias[col+1];
                v0 = fmaxf(v0 + b0, 0.f); v1 = fmaxf(v1 + b1, 0.f);
                v2 = fmaxf(v2 + b0, 0.f); v3 = fmaxf(v3 + b1, 0.f);
            }
            if (EPI == 2) {
                float b0 = bias[col], b1 = bias[col+1];
                v0 = softplusf(v0 + b0); v1 = softplusf(v1 + b1);
                v2 = softplusf(v2 + b0); v3 = softplusf(v3 + b1);
            }
            if (EPI == 3) {
                const float2 r0 = *(const float2*)&res[(size_t)row * N + col];
                const float2 r1 = *(const float2*)&res[(size_t)(row+8) * N + col];
                v0 += r0.x; v1 += r0.y; v2 += r1.x; v3 += r1.y;
            }
            if (sizeof(OutT) == 4) {
                float2* o0 = (float2*)((float*)C + (size_t)row * N + col);
                float2* o1 = (float2*)((float*)C + (size_t)(row+8) * N + col);
                *o0 = make_float2(v0, v1);
                *o1 = make_float2(v2, v3);
            } else {
                *(__nv_bfloat162*)((bf16*)C + (size_t)row * N + col) =
                    __floats2bfloat162_rn(v0, v1);
                *(__nv_bfloat162*)((bf16*)C + (size_t)(row+8) * N + col) =
                    __floats2bfloat162_rn(v2, v3);
            }
        }
    }
}

// ---------------- depthwise conv (k=3, pad=1) + SiLU: 4 channels/thread -----
__global__ void conv_silu_kernel(const bf16* __restrict__ hin,
                                 const float* __restrict__ w,
                                 bf16* __restrict__ out) {
    size_t t = (size_t)blockIdx.x * blockDim.x + threadIdx.x;
    if (t >= (size_t)MM * HH / 4) return;
    int h4 = (int)(t & (HH/4 - 1));
    size_t row = t >> 8;
    int l = (int)(row & (LL - 1));
    int h = h4 * 4;
    float4 wv0 = *(const float4*)(w + h*3);
    float4 wv1 = *(const float4*)(w + h*3 + 4);
    float4 wv2 = *(const float4*)(w + h*3 + 8);
    const uint2* hp = (const uint2*)hin;
    uint2 zero = make_uint2(0u, 0u);
    uint2 m  = hp[t];
    uint2 lf = (l > 0)      ? hp[t - HH/4] : zero;
    uint2 rt = (l < LL - 1) ? hp[t + HH/4] : zero;
    float2 m0 = __bfloat1622float2(*(__nv_bfloat162*)&m.x);
    float2 m1 = __bfloat1622float2(*(__nv_bfloat162*)&m.y);
    float2 l0 = __bfloat1622float2(*(__nv_bfloat162*)&lf.x);
    float2 l1 = __bfloat1622float2(*(__nv_bfloat162*)&lf.y);
    float2 r0 = __bfloat1622float2(*(__nv_bfloat162*)&rt.x);
    float2 r1 = __bfloat1622float2(*(__nv_bfloat162*)&rt.y);
    float v0 = wv0.x*l0.x + wv0.y*m0.x + wv0.z*r0.x;
    float v1 = wv0.w*l0.y + wv1.x*m0.y + wv1.y*r0.y;
    float v2 = wv1.z*l1.x + wv1.w*m1.x + wv2.x*r1.x;
    float v3 = wv2.y*l1.y + wv2.z*m1.y + wv2.w*r1.y;
    v0 = v0 / (1.f + __expf(-v0));
    v1 = v1 / (1.f + __expf(-v1));
    v2 = v2 / (1.f + __expf(-v2));
    v3 = v3 / (1.f + __expf(-v3));
    uint2 o;
    *(__nv_bfloat162*)&o.x = __floats2bfloat162_rn(v0, v1);
    *(__nv_bfloat162*)&o.y = __floats2bfloat162_rn(v2, v3);
    ((uint2*)out)[t] = o;
}

// ---------------- selective scan: thread per (b, h, n) [R4 structure] -------
// Only change vs proven R4: log2(e) folded into aneg, raw ex2.approx.
__global__ void scan_kernel(const bf16* __restrict__ xin,
                            const bf16* __restrict__ dt,
                            const float* __restrict__ Aw,
                            const float* __restrict__ Dw,
                            bf16* __restrict__ y) {
    int t = blockIdx.x * blockDim.x + threadIdx.x;
    int n  = t & (NS - 1);
    int hb = t >> 4;
    int h  = hb & (HH - 1);
    int b  = hb >> 10;

    float a    = Aw[h * NS + n];
    float aneg = -expf(a);
    float anl2 = aneg * 1.4426950408889634f;   // fold log2(e)
    float inva = (fabsf(aneg) < 1e-5f) ? 1.f : 1.f / aneg;
    float d    = Dw[h];

    const bf16* xp = xin + (size_t)b * LL * HH + h;
    const bf16* dp = dt  + (size_t)b * LL * HH + h;
    bf16*       yp = y   + (size_t)b * LL * HH + h;

    float state = 0.f;
    for (int l = 0; l < LL; l++) {
        size_t off = (size_t)l * HH;
        float xt  = __bfloat162float(xp[off]);
        float dtt = __bfloat162float(dp[off]);
        float e;
        asm("ex2.approx.f32 %0, %1;" : "=f"(e) : "f"(anl2 * dtt));
        float db  = (e - 1.f) * inva * dtt;
        state = fmaf(e, state, db * xt);
        float p = state * a;
        p += __shfl_xor_sync(0xffffffffu, p, 8);
        p += __shfl_xor_sync(0xffffffffu, p, 4);
        p += __shfl_xor_sync(0xffffffffu, p, 2);
        p += __shfl_xor_sync(0xffffffffu, p, 1);
        if (n == 0) yp[off] = __float2bfloat16(fmaf(d, xt, p));
    }
}

// ---------------- launch ----------------------------------------------------
extern "C" void kernel_launch(void* const* d_in, const int* in_sizes, int n_in,
                              void* d_out, int out_size) {
    const float* x      = (const float*)d_in[0];
    const float* ln_g   = (const float*)d_in[1];
    const float* ln_b   = (const float*)d_in[2];
    const float* W_in   = (const float*)d_in[3];
    const float* conv_w = (const float*)d_in[4];
    const float* A      = (const float*)d_in[5];
    const float* D      = (const float*)d_in[6];
    const float* dt_W1  = (const float*)d_in[7];
    const float* dt_b1  = (const float*)d_in[8];
    const float* dt_W2  = (const float*)d_in[9];
    const float* dt_b2  = (const float*)d_in[10];
    const float* W_out  = (const float*)d_in[11];
    float* out = (float*)d_out;

    bf16 *p_xn, *p_h, *p_hc, *p_dtr, *p_dt, *p_y;
    bf16 *p_win, *p_w1, *p_w2, *p_wout;
    cudaGetSymbolAddress((void**)&p_xn,  g_xn16);
    cudaGetSymbolAddress((void**)&p_h,   g_h16);
    cudaGetSymbolAddress((void**)&p_hc,  g_hc16);
    cudaGetSymbolAddress((void**)&p_dtr, g_dtr16);
    cudaGetSymbolAddress((void**)&p_dt,  g_dt16);
    cudaGetSymbolAddress((void**)&p_y,   g_y16);
    cudaGetSymbolAddress((void**)&p_win, g_win16);
    cudaGetSymbolAddress((void**)&p_w1,  g_w1_16);
    cudaGetSymbolAddress((void**)&p_w2,  g_w2_16);
    cudaGetSymbolAddress((void**)&p_wout,g_wout16);

    // 0) weight conversion f32 -> bf16 (merged, float4)
    f2bf4_kernel<<<(SEG3/4 + 255)/256, 256>>>(W_in, dt_W1, dt_W2, W_out,
                                              p_win, p_w1, p_w2, p_wout);

    // 1) LayerNorm (f32 in, bf16 out)
    ln_kernel<<<MM, 128>>>(x, ln_g, ln_b, p_xn);

    // 2) in_proj: h = xn @ W_in^T   [16384,512] x [1024,512]^T
    gemm_bf16<0, 2, bf16><<<dim3(HH/128, MM/128), 256>>>(
        p_xn, p_win, nullptr, nullptr, p_h, MM, HH, DIN);

    // 3) depthwise conv + SiLU (4 channels/thread)
    conv_silu_kernel<<<(MM * HH / 4) / 256, 256>>>(p_h, conv_w, p_hc);

    // 4) dt hidden: relu(hc @ dt_W1^T + b1)   N=64 -> BN=64 tile (PB=1)
    gemm_bf16<1, 1, bf16><<<dim3(1, MM/128), 256>>>(
        p_hc, p_w1, dt_b1, nullptr, p_dtr, MM, RR, HH);

    // 5) dt: softplus(dtr @ dt_W2^T + b2)
    gemm_bf16<2, 2, bf16><<<dim3(HH/128, MM/128), 256>>>(
        p_dtr, p_w2, dt_b2, nullptr, p_dt, MM, HH, RR);

    // 6) selective scan (R4 structure + ex2 fold)
    scan_kernel<<<(BB * HH * NS) / 256, 256>>>(p_hc, p_dt, A, D, p_y);

    // 7) out proj + residual: out = y @ W_out^T + x
    gemm_bf16<3, 2, float><<<dim3(DIN/128, MM/128), 256>>>(
        p_y, p_wout, nullptr, x, out, MM, DIN, HH);
}